// round 8
// baseline (speedup 1.0000x reference)
#include <cuda_runtime.h>

// Scatter (128, 524800) fp32 into upper triangles of (128, 1024, 1024).
// Row-major triu: input flat index of (r,c), c>=r, is base(r) + (c-r),
// base(r) = r*M - r*(r-1)/2. Pure bandwidth: 256 MiB read + 512 MiB write.
//
// R5: persistent grid-stride, 4 independent float4 per loop iteration
// (batched loads -> batched stores) to keep HBM request queues full;
// streaming cache hints (no reuse). 2048 CTAs so each CTA is long-lived.

#define MATSIZE 1024
#define TRIU_LEN 524800
#define BATCH 128

__device__ __forceinline__ float4 compute_v(const float* __restrict__ in, long gid)
{
    const int b   = (int)(gid >> 18);          // / 262144  (float4s per matrix)
    const int rem = (int)(gid & 0x3FFFF);
    const int r   = rem >> 8;                  // row (256 float4 per row)
    const int c0  = (rem & 0xFF) << 2;         // first of 4 columns

    float4 v;
    if (c0 >= r) {
        // Fully inside the upper triangle: 4 contiguous input floats.
        const int base = r * MATSIZE - ((r * (r - 1)) >> 1);
        const float* p = in + (long)b * TRIU_LEN + base + (c0 - r);
        v.x = __ldcs(p + 0);
        v.y = __ldcs(p + 1);
        v.z = __ldcs(p + 2);
        v.w = __ldcs(p + 3);
    } else if (c0 + 3 < r) {
        v = make_float4(0.f, 0.f, 0.f, 0.f);
    } else {
        // Straddles the diagonal (1 thread per row per matrix).
        const int base = r * MATSIZE - ((r * (r - 1)) >> 1);
        const float* rowin = in + (long)b * TRIU_LEN + base - r;
        v.x = (c0     >= r) ? __ldcs(rowin + c0    ) : 0.f;
        v.y = (c0 + 1 >= r) ? __ldcs(rowin + c0 + 1) : 0.f;
        v.z = (c0 + 2 >= r) ? __ldcs(rowin + c0 + 2) : 0.f;
        v.w = (c0 + 3 >= r) ? __ldcs(rowin + c0 + 3) : 0.f;
    }
    return v;
}

__global__ void __launch_bounds__(256)
triu_scatter_kernel(const float* __restrict__ in, float* __restrict__ out)
{
    const long total4 = (long)BATCH * (MATSIZE * MATSIZE / 4);   // 2^25
    const long stride = (long)gridDim.x * blockDim.x;            // 2^19 for grid=2048
    long gid = (long)blockIdx.x * blockDim.x + threadIdx.x;

    // Main unrolled loop: 4 independent float4s per iteration.
    for (; gid + 3 * stride < total4; gid += 4 * stride) {
        float4 v0 = compute_v(in, gid);
        float4 v1 = compute_v(in, gid + stride);
        float4 v2 = compute_v(in, gid + 2 * stride);
        float4 v3 = compute_v(in, gid + 3 * stride);
        __stcs(reinterpret_cast<float4*>(out) + gid,              v0);
        __stcs(reinterpret_cast<float4*>(out) + gid + stride,     v1);
        __stcs(reinterpret_cast<float4*>(out) + gid + 2 * stride, v2);
        __stcs(reinterpret_cast<float4*>(out) + gid + 3 * stride, v3);
    }
    // Tail (empty when stride divides total4, kept for safety).
    for (; gid < total4; gid += stride)
        __stcs(reinterpret_cast<float4*>(out) + gid, compute_v(in, gid));
}

extern "C" void kernel_launch(void* const* d_in, const int* in_sizes, int n_in,
                              void* d_out, int out_size)
{
    const float* in = (const float*)d_in[0];
    float* out = (float*)d_out;

    const int threads = 256;
    const int blocks  = 2048;   // stride = 2^19; 2^25 / (4*2^19) = 16 iterations, no tail

    triu_scatter_kernel<<<blocks, threads>>>(in, out);
}